// round 3
// baseline (speedup 1.0000x reference)
#include <cuda_runtime.h>
#include <cstdint>

#define T_STEPS 1000
#define B       64
#define NIN     512
#define NOUT    128
#define KS      16      // i-slices (k-split of NIN)
#define OT      8       // o-tiles
#define OTS     16      // o per tile
#define ISW     32      // i per slice
#define NCTA    128     // KS * OT
#define TPB     256
#define LRATE   1e-3f

// Persistent device state (no cudaMalloc allowed)
__device__ float g_psp[(size_t)T_STEPS * B * NIN];   // 131 MB precomputed PSP traces
__device__ float g_zin_part[KS * B * NOUT];          // per-k-slice z_in partials
__device__ float g_zout[B * NOUT];                   // current step softmax output
__device__ float g_bias[NOUT];
__device__ unsigned g_ctr;                           // grid barrier counter

__global__ void init_kernel(const float* __restrict__ bias) {
    int t = threadIdx.x;
    if (t < NOUT) g_bias[t] = bias[t];
    if (t == 0) g_ctr = 0u;
}

// PSP trace: independent scan over T for each (b, i) pair. 32768 threads.
__global__ void psp_kernel(const float* __restrict__ spikes) {
    int idx = blockIdx.x * blockDim.x + threadIdx.x;   // 0..32767
    float tr = 0.f;
    const float* sp = spikes + idx;
    float* pp = g_psp + idx;
#pragma unroll 4
    for (int t = 0; t < T_STEPS; t++) {
        tr = 0.9f * tr + sp[(size_t)t * (B * NIN)];
        pp[(size_t)t * (B * NIN)] = tr;
    }
}

// Software grid barrier. All NCTA CTAs are co-resident (128 <= 148/152 SMs,
// launch_bounds + small smem guarantee wave-1 placement). The post-spin
// __threadfence (fence.sc.gpu -> CCTL.IVALL on sm_103a) invalidates L1 so
// subsequent weak loads by ALL threads of this CTA see remote writes.
__device__ __forceinline__ void grid_barrier(unsigned target) {
    __syncthreads();
    if (threadIdx.x == 0) {
        __threadfence();   // release my CTA's prior writes
        asm volatile("red.release.gpu.add.u32 [%0], %1;" :: "l"(&g_ctr), "r"(1u) : "memory");
        unsigned v;
        do {
            asm volatile("ld.acquire.gpu.u32 %0, [%1];" : "=r"(v) : "l"(&g_ctr) : "memory");
        } while (v < target);
        __threadfence();   // acquire: flush stale L1 for the whole SM
    }
    __syncthreads();
}

__global__ void __launch_bounds__(TPB, 1)
snn_kernel(const float* __restrict__ weight, float* __restrict__ out, int out_size) {
    __shared__ float sW[OTS][ISW + 4];   // this CTA's W slice (padded vs bank conflicts)
    __shared__ float sP[2][B][ISW];      // double-buffered psp slice (t and t-1)
    __shared__ float sZ[B][OTS];         // z_out columns for this o-tile
    __shared__ float sRed[8];            // softmax cross-warp scratch

    const int cta = blockIdx.x;
    const int tid = threadIdx.x;
    const int ot = cta & (OT - 1);       // o-tile id
    const int is = cta >> 3;             // i-slice id
    const int o0 = ot * OTS;
    const int i0 = is * ISW;

    // Load this CTA's W slice into smem — W lives here for the whole kernel.
    for (int idx = tid; idx < OTS * ISW; idx += TPB) {
        int ol = idx >> 5, il = idx & 31;
        sW[ol][il] = weight[(o0 + ol) * NIN + i0 + il];
    }

    const int olA = tid >> 4;            // STDP phase: o_local (0..15)
    const int iA  = (tid & 15) * 2;      // STDP phase: i pair
    const int olB = tid & 15;            // GEMM phase: o_local
    const int b0  = tid >> 4;            // GEMM phase: base batch row
    const bool wr_bias = (is == 0) && ((tid & 15) == 0);

    float u_reg = 0.f;                   // membrane potential u[cta][tid] (cta<64, tid<128)
    unsigned ep = 0;

    __syncthreads();

    for (int t = 0; t < T_STEPS; t++) {
        const int cur = t & 1;

        // ---- stage A: loads (z_out tile of step t-1, psp[t] slice) ----
        if (t > 0) {
            int b = tid >> 2, c4 = tid & 3;          // 256 float4 = 64x16 tile
            *(float4*)&sZ[b][c4 * 4] =
                *(const float4*)&g_zout[b * NOUT + o0 + c4 * 4];
        }
        {
            const float* src = g_psp + (size_t)t * (B * NIN) + i0;
#pragma unroll
            for (int j = 0; j < 2; j++) {
                int idx = tid + j * TPB;             // 512 float4 = 64x32 slice
                int b = idx >> 3, c4 = idx & 7;
                *(float4*)&sP[cur][b][c4 * 4] =
                    *(const float4*)&src[b * NIN + c4 * 4];
            }
        }
        __syncthreads();

        // ---- stage B: Nessler STDP update of this CTA's W slice (uses step t-1) ----
        if (t > 0) {
            const float* P = &sP[cur ^ 1][0][0];     // psp of step t-1
            float acc0 = 0.f, acc1 = 0.f, pm = 0.f;
#pragma unroll 8
            for (int b = 0; b < B; b++) {
                float z = sZ[b][olA];
                pm += z;
                float2 p = *(const float2*)&P[b * ISW + iA];
                acc0 += z * p.x;
                acc1 += z * p.y;
            }
            pm *= (1.f / B);
            float w0 = sW[olA][iA], w1 = sW[olA][iA + 1];
            w0 += LRATE * (__expf(-w0) * acc0 * (1.f / B) - pm);
            w1 += LRATE * (__expf(-w1) * acc1 * (1.f / B) - pm);
            sW[olA][iA]     = w0;
            sW[olA][iA + 1] = w1;
            if (wr_bias) {
                float bb = g_bias[o0 + olA];
                g_bias[o0 + olA] = bb + LRATE * (__expf(-bb) - 1.f) * pm;
            }
        }
        __syncthreads();

        // ---- stage C: z_in partials for this (o-tile, k-slice) ----
        {
            const float* P = &sP[cur][0][0];
            float4 w[8];
#pragma unroll
            for (int q = 0; q < 8; q++) w[q] = *(const float4*)&sW[olB][q * 4];
#pragma unroll
            for (int j = 0; j < 4; j++) {
                int b = b0 + j * 16;
                const float* pr = &P[b * ISW];
                float acc = 0.f;
#pragma unroll
                for (int q = 0; q < 8; q++) {
                    float4 p = *(const float4*)&pr[q * 4];
                    acc += p.x * w[q].x; acc += p.y * w[q].y;
                    acc += p.z * w[q].z; acc += p.w * w[q].w;
                }
                g_zin_part[(is * B + b) * NOUT + o0 + olB] = acc;
            }
        }
        grid_barrier(++ep * NCTA);

        // ---- stage D: reduce partials, membrane, softmax (CTA b = 0..63) ----
        if (cta < B) {
            float e = 0.f;
            if (tid < NOUT) {
                float z = g_bias[tid];
#pragma unroll
                for (int s = 0; s < KS; s++)
                    z += g_zin_part[(s * B + cta) * NOUT + tid];
                u_reg = 0.9f * u_reg + z;
                float m = u_reg;
#pragma unroll
                for (int o = 16; o > 0; o >>= 1)
                    m = fmaxf(m, __shfl_xor_sync(0xffffffffu, m, o));
                if ((tid & 31) == 0) sRed[tid >> 5] = m;
            }
            __syncthreads();
            float mx = fmaxf(fmaxf(sRed[0], sRed[1]), fmaxf(sRed[2], sRed[3]));
            if (tid < NOUT) {
                e = __expf(u_reg - mx);
                float s = e;
#pragma unroll
                for (int o = 16; o > 0; o >>= 1)
                    s += __shfl_xor_sync(0xffffffffu, s, o);
                if ((tid & 31) == 0) sRed[4 + (tid >> 5)] = s;
            }
            __syncthreads();
            if (tid < NOUT) {
                float z = e / (sRed[4] + sRed[5] + sRed[6] + sRed[7]);
                g_zout[cta * NOUT + tid] = z;
                out[(size_t)t * (B * NOUT) + cta * NOUT + tid] = z;
                if (t == T_STEPS - 1 && out_size >= (T_STEPS + 1) * B * NOUT)
                    out[(size_t)T_STEPS * (B * NOUT) + cta * NOUT + tid] = u_reg;
            }
        }
        grid_barrier(++ep * NCTA);
    }
}

extern "C" void kernel_launch(void* const* d_in, const int* in_sizes, int n_in,
                              void* d_out, int out_size) {
    const float* spikes = nullptr;
    const float* weight = nullptr;
    const float* bias   = nullptr;
    for (int i = 0; i < n_in; i++) {
        long n = in_sizes[i];
        if      (n == (long)T_STEPS * B * NIN) spikes = (const float*)d_in[i];
        else if (n == (long)NOUT * NIN)        weight = (const float*)d_in[i];
        else if (n == (long)NOUT)              bias   = (const float*)d_in[i];
    }
    init_kernel<<<1, 128>>>(bias);
    psp_kernel<<<64, 512>>>(spikes);
    snn_kernel<<<NCTA, TPB>>>(weight, (float*)d_out, out_size);
}

// round 9
// speedup vs baseline: 1.0254x; 1.0254x over previous
#include <cuda_runtime.h>
#include <cstdint>

#define T_STEPS 1000
#define B       64
#define NIN     512
#define NOUT    128
#define KS      16      // i-slices (k-split of NIN)
#define OT      8       // o-tiles
#define OTS     16      // o per tile
#define ISW     32      // i per slice
#define NCTA    128     // KS * OT
#define TPB     256
#define LRATE   1e-3f

// Persistent device state (no cudaMalloc allowed)
__device__ float g_psp[(size_t)T_STEPS * B * NIN];   // 131 MB precomputed PSP traces
__device__ float g_zin_part[KS * B * NOUT];          // per-k-slice z_in partials
__device__ float g_zout[B * NOUT];                   // current step softmax output
__device__ float g_bias[NOUT];
__device__ unsigned g_ctr;                           // grid barrier counter

__global__ void init_kernel(const float* __restrict__ bias) {
    int t = threadIdx.x;
    if (t < NOUT) g_bias[t] = bias[t];
    if (t == 0) g_ctr = 0u;
}

// PSP trace: independent scan over T for each (b, i) pair. 32768 threads.
__global__ void psp_kernel(const float* __restrict__ spikes) {
    int idx = blockIdx.x * blockDim.x + threadIdx.x;   // 0..32767
    float tr = 0.f;
    const float* sp = spikes + idx;
    float* pp = g_psp + idx;
#pragma unroll 4
    for (int t = 0; t < T_STEPS; t++) {
        tr = 0.9f * tr + sp[(size_t)t * (B * NIN)];
        pp[(size_t)t * (B * NIN)] = tr;
    }
}

// Software grid barrier — PROVEN R3 protocol. release-red arrive, acquire-ld
// spin, post-spin __threadfence for acquire cumulativity (all threads of the
// CTA subsequently see all pre-barrier writes of all CTAs).
__device__ __forceinline__ void grid_barrier(unsigned target) {
    __syncthreads();
    if (threadIdx.x == 0) {
        __threadfence();   // release my CTA's prior writes (cumulative w/ bar.sync)
        asm volatile("red.release.gpu.add.u32 [%0], %1;" :: "l"(&g_ctr), "r"(1u) : "memory");
        unsigned v;
        do {
            asm volatile("ld.acquire.gpu.u32 %0, [%1];" : "=r"(v) : "l"(&g_ctr) : "memory");
        } while (v < target);
        __threadfence();   // acquire side: flush stale L1 for the whole SM
    }
    __syncthreads();
}

__global__ void __launch_bounds__(TPB, 1)
snn_kernel(const float* __restrict__ weight, float* __restrict__ out, int out_size) {
    __shared__ float sW[OTS][ISW + 4];   // this CTA's W slice (persistent, padded)
    __shared__ float sP[2][B][ISW];      // double-buffered psp slice (t and t-1)
    __shared__ float sZ[B][OTS];         // z_out columns for this o-tile
    __shared__ float sRed[8];            // softmax cross-warp scratch

    const int cta = blockIdx.x;
    const int tid = threadIdx.x;
    const int ot = cta & (OT - 1);       // o-tile id
    const int is = cta >> 3;             // i-slice id
    const int o0 = ot * OTS;
    const int i0 = is * ISW;

    // W slice lives in smem for the whole kernel.
    for (int idx = tid; idx < OTS * ISW; idx += TPB) {
        int ol = idx >> 5, il = idx & 31;
        sW[ol][il] = weight[(o0 + ol) * NIN + i0 + il];
    }

    const int olA = tid >> 4;            // STDP phase: o_local (0..15)
    const int iA  = (tid & 15) * 2;      // STDP phase: i pair
    const int olB = tid & 15;            // GEMM phase: o_local
    const int b0  = tid >> 4;            // GEMM phase: base batch row
    const bool wr_bias = (is == 0) && ((tid & 15) == 0);

    // psp smem-commit / prefetch geometry (512 float4 per slice, 2 per thread)
    const int pb0 = tid >> 3,          pc0 = (tid & 7) * 4;
    const int pb1 = (tid + TPB) >> 3,  pc1 = ((tid + TPB) & 7) * 4;

    // prefetch psp[0] into registers (latency hidden behind sW load + barrier skew)
    float4 pf0, pf1;
    {
        const float* src = g_psp + i0;
        pf0 = *(const float4*)&src[pb0 * NIN + pc0];
        pf1 = *(const float4*)&src[pb1 * NIN + pc1];
    }

    float u_reg = 0.f;                   // membrane u[cta][tid] (cta<64, tid<128)
    unsigned ep = 0;

    __syncthreads();

    for (int t = 0; t < T_STEPS; t++) {
        const int cur = t & 1;

        // ---- stage A: sZ load (z_out of t-1), commit prefetched psp[t],
        //               issue prefetch of psp[t+1] ----
        if (t > 0) {
            int b = tid >> 2, c4 = tid & 3;          // 256 float4 = 64x16 tile
            *(float4*)&sZ[b][c4 * 4] =
                *(const float4*)&g_zout[b * NOUT + o0 + c4 * 4];
        }
        *(float4*)&sP[cur][pb0][pc0] = pf0;
        *(float4*)&sP[cur][pb1][pc1] = pf1;
        if (t + 1 < T_STEPS) {
            const float* src = g_psp + (size_t)(t + 1) * (B * NIN) + i0;
            pf0 = *(const float4*)&src[pb0 * NIN + pc0];
            pf1 = *(const float4*)&src[pb1 * NIN + pc1];
        }
        __syncthreads();

        // ---- stage B: Nessler STDP update of this CTA's W slice (uses step t-1) ----
        if (t > 0) {
            const float* P = &sP[cur ^ 1][0][0];     // psp of step t-1
            float acc0 = 0.f, acc1 = 0.f, pm = 0.f;
#pragma unroll 8
            for (int b = 0; b < B; b++) {
                float z = sZ[b][olA];
                pm += z;
                float2 p = *(const float2*)&P[b * ISW + iA];
                acc0 += z * p.x;
                acc1 += z * p.y;
            }
            pm *= (1.f / B);
            float w0 = sW[olA][iA], w1 = sW[olA][iA + 1];
            w0 += LRATE * (__expf(-w0) * acc0 * (1.f / B) - pm);
            w1 += LRATE * (__expf(-w1) * acc1 * (1.f / B) - pm);
            sW[olA][iA]     = w0;
            sW[olA][iA + 1] = w1;
            if (wr_bias) {
                float bb = g_bias[o0 + olA];
                g_bias[o0 + olA] = bb + LRATE * (__expf(-bb) - 1.f) * pm;
            }
        }
        __syncthreads();

        // ---- stage C: z_in partials for this (o-tile, k-slice) ----
        {
            const float* P = &sP[cur][0][0];
            float4 w[8];
#pragma unroll
            for (int q = 0; q < 8; q++) w[q] = *(const float4*)&sW[olB][q * 4];
#pragma unroll
            for (int j = 0; j < 4; j++) {
                int b = b0 + j * 16;
                const float* pr = &P[b * ISW];
                float acc = 0.f;
#pragma unroll
                for (int q = 0; q < 8; q++) {
                    float4 p = *(const float4*)&pr[q * 4];
                    acc += p.x * w[q].x; acc += p.y * w[q].y;
                    acc += p.z * w[q].z; acc += p.w * w[q].w;
                }
                g_zin_part[(is * B + b) * NOUT + o0 + olB] = acc;
            }
        }
        grid_barrier(++ep * NCTA);

        // ---- stage D: reduce partials, membrane, softmax (CTA b = 0..63) ----
        if (cta < B) {
            float e = 0.f;
            if (tid < NOUT) {
                float z = g_bias[tid];
#pragma unroll
                for (int s = 0; s < KS; s++)
                    z += g_zin_part[(s * B + cta) * NOUT + tid];
                u_reg = 0.9f * u_reg + z;
                float m = u_reg;
#pragma unroll
                for (int o = 16; o > 0; o >>= 1)
                    m = fmaxf(m, __shfl_xor_sync(0xffffffffu, m, o));
                if ((tid & 31) == 0) sRed[tid >> 5] = m;
            }
            __syncthreads();
            float mx = fmaxf(fmaxf(sRed[0], sRed[1]), fmaxf(sRed[2], sRed[3]));
            if (tid < NOUT) {
                e = __expf(u_reg - mx);
                float s = e;
#pragma unroll
                for (int o = 16; o > 0; o >>= 1)
                    s += __shfl_xor_sync(0xffffffffu, s, o);
                if ((tid & 31) == 0) sRed[4 + (tid >> 5)] = s;
            }
            __syncthreads();
            if (tid < NOUT) {
                float z = e / (sRed[4] + sRed[5] + sRed[6] + sRed[7]);
                g_zout[cta * NOUT + tid] = z;
                out[(size_t)t * (B * NOUT) + cta * NOUT + tid] = z;
                if (t == T_STEPS - 1 && out_size >= (T_STEPS + 1) * B * NOUT)
                    out[(size_t)T_STEPS * (B * NOUT) + cta * NOUT + tid] = u_reg;
            }
        }
        grid_barrier(++ep * NCTA);
    }
}

extern "C" void kernel_launch(void* const* d_in, const int* in_sizes, int n_in,
                              void* d_out, int out_size) {
    const float* spikes = nullptr;
    const float* weight = nullptr;
    const float* bias   = nullptr;
    for (int i = 0; i < n_in; i++) {
        long n = in_sizes[i];
        if      (n == (long)T_STEPS * B * NIN) spikes = (const float*)d_in[i];
        else if (n == (long)NOUT * NIN)        weight = (const float*)d_in[i];
        else if (n == (long)NOUT)              bias   = (const float*)d_in[i];
    }
    init_kernel<<<1, 128>>>(bias);
    psp_kernel<<<64, 512>>>(spikes);
    snn_kernel<<<NCTA, TPB>>>(weight, (float*)d_out, out_size);
}

// round 12
// speedup vs baseline: 1.0298x; 1.0043x over previous
#include <cuda_runtime.h>
#include <cstdint>

#define T_STEPS 1000
#define B       64
#define NIN     512
#define NOUT    128
#define KS      16      // i-slices (k-split of NIN)
#define OT      8       // o-tiles
#define OTS     16      // o per tile
#define ISW     32      // i per slice
#define NCTA    128     // KS * OT
#define TPB     256
#define LRATE   1e-3f

// interleaved column index: conflict-free smem layout for 32-col-per-thread access
#define ILV(o)  ((((o) & 31) << 2) | ((o) >> 5))

// Persistent device state (no cudaMalloc allowed)
__device__ float g_psp[(size_t)T_STEPS * B * NIN];   // 131 MB precomputed PSP traces
__device__ float g_zin[3][B * NOUT];                 // triple-buffered z_in accumulators
__device__ unsigned g_ctr;                           // grid barrier counter

__global__ void init_kernel() {
    int idx = blockIdx.x * blockDim.x + threadIdx.x;   // 96*256 = 24576 = 3*8192
    ((float*)g_zin)[idx] = 0.f;
    if (idx == 0) g_ctr = 0u;
}

// PSP trace: independent scan over T for each (b, i) pair. 32768 threads.
__global__ void psp_kernel(const float* __restrict__ spikes) {
    int idx = blockIdx.x * blockDim.x + threadIdx.x;   // 0..32767
    float tr = 0.f;
    const float* sp = spikes + idx;
    float* pp = g_psp + idx;
#pragma unroll 4
    for (int t = 0; t < T_STEPS; t++) {
        tr = 0.9f * tr + sp[(size_t)t * (B * NIN)];
        pp[(size_t)t * (B * NIN)] = tr;
    }
}

// Software grid barrier — PROVEN R3 protocol (byte-identical). release-red
// arrive, acquire-ld spin, post-spin __threadfence for acquire cumulativity.
__device__ __forceinline__ void grid_barrier(unsigned target) {
    __syncthreads();
    if (threadIdx.x == 0) {
        __threadfence();   // release my CTA's prior writes (cumulative w/ bar.sync)
        asm volatile("red.release.gpu.add.u32 [%0], %1;" :: "l"(&g_ctr), "r"(1u) : "memory");
        unsigned v;
        do {
            asm volatile("ld.acquire.gpu.u32 %0, [%1];" : "=r"(v) : "l"(&g_ctr) : "memory");
        } while (v < target);
        __threadfence();   // acquire side: flush stale L1 for the whole SM
    }
    __syncthreads();
}

__device__ __forceinline__ void red_add_f32(float* p, float v) {
    asm volatile("red.global.add.f32 [%0], %1;" :: "l"(p), "f"(v) : "memory");
}

__global__ void __launch_bounds__(TPB, 1)
snn_kernel(const float* __restrict__ weight, const float* __restrict__ bias_in,
           float* __restrict__ out, int out_size) {
    __shared__ float sW[OTS][ISW + 4];       // this CTA's W slice (persistent)
    __shared__ float sP[B][ISW];             // psp slice (single buffer)
    __shared__ float sZ[B][NOUT + 4];        // FULL z_out, interleaved cols (local!)
    __shared__ float sBias[NOUT];            // full bias, replicated per CTA
    __shared__ float sPm[NOUT];              // post-mean of z_out, replicated

    const int cta = blockIdx.x;
    const int tid = threadIdx.x;
    const int ot = cta & (OT - 1);
    const int is = cta >> 3;
    const int o0 = ot * OTS;
    const int i0 = is * ISW;

    for (int idx = tid; idx < OTS * ISW; idx += TPB) {
        int ol = idx >> 5, il = idx & 31;
        sW[ol][il] = weight[(o0 + ol) * NIN + i0 + il];
    }
    if (tid < NOUT) sBias[ILV(tid)] = bias_in[tid];

    // phase-role ids
    const int olA = tid >> 4;                 // STDP: o_local
    const int iA  = (tid & 15) * 2;           // STDP: i pair
    const int ilvA = ILV(o0 + olA);
    const int olB = tid & 15;                 // GEMM: o_local
    const int b0  = tid >> 4;                 // GEMM: base batch row
    const int eb  = tid >> 2;                 // E: batch row (0..63)
    const int ec4 = tid & 3;                  // E: 32-col slice id

    // psp commit/prefetch geometry (512 float4/slice, 2 per thread)
    const int pb0 = tid >> 3,          pc0 = (tid & 7) * 4;
    const int pb1 = (tid + TPB) >> 3,  pc1 = ((tid + TPB) & 7) * 4;

    float4 pf0, pf1;
    {
        const float* src = g_psp + i0;
        pf0 = *(const float4*)&src[pb0 * NIN + pc0];
        pf1 = *(const float4*)&src[pb1 * NIN + pc1];
    }

    float u[32];                              // membrane: rows eb, cols ec4*32+j
#pragma unroll
    for (int j = 0; j < 32; j++) u[j] = 0.f;

    unsigned ep = 0;
    __syncthreads();

    for (int t = 0; t < T_STEPS; t++) {
        // ---- stage B: STDP update of sW + bias (uses z(t-1), psp(t-1)) ----
        if (t > 0) {
            float acc0 = 0.f, acc1 = 0.f;
#pragma unroll 8
            for (int b = 0; b < B; b++) {
                float z = sZ[b][ilvA];
                float2 p = *(const float2*)&sP[b][iA];
                acc0 += z * p.x;
                acc1 += z * p.y;
            }
            float pm = sPm[ilvA];
            float w0 = sW[olA][iA], w1 = sW[olA][iA + 1];
            w0 += LRATE * (__expf(-w0) * acc0 * (1.f / B) - pm);
            w1 += LRATE * (__expf(-w1) * acc1 * (1.f / B) - pm);
            sW[olA][iA]     = w0;
            sW[olA][iA + 1] = w1;
            if (tid < NOUT) {
                int iv = ILV(tid);
                float bb = sBias[iv];
                sBias[iv] = bb + LRATE * (__expf(-bb) - 1.f) * sPm[iv];
            }
        }
        __syncthreads();

        // ---- stage A: commit psp(t) to sP, prefetch psp(t+1) ----
        *(float4*)&sP[pb0][pc0] = pf0;
        *(float4*)&sP[pb1][pc1] = pf1;
        if (t + 1 < T_STEPS) {
            const float* src = g_psp + (size_t)(t + 1) * (B * NIN) + i0;
            pf0 = *(const float4*)&src[pb0 * NIN + pc0];
            pf1 = *(const float4*)&src[pb1 * NIN + pc1];
        }
        __syncthreads();

        // ---- stage C: z_in partial GEMM, accumulate via global red.add ----
        {
            float* zacc = g_zin[t % 3];
            float4 w[8];
#pragma unroll
            for (int q = 0; q < 8; q++) w[q] = *(const float4*)&sW[olB][q * 4];
#pragma unroll
            for (int j = 0; j < 4; j++) {
                int b = b0 + j * 16;
                const float* pr = &sP[b][0];
                float acc = 0.f;
#pragma unroll
                for (int q = 0; q < 8; q++) {
                    float4 p = *(const float4*)&pr[q * 4];
                    acc += p.x * w[q].x; acc += p.y * w[q].y;
                    acc += p.z * w[q].z; acc += p.w * w[q].w;
                }
                red_add_f32(&zacc[b * NOUT + o0 + olB], acc);
            }
        }

        // ---- the ONE global barrier per step ----
        grid_barrier(++ep * NCTA);

        // ---- stage E: local membrane + softmax (every CTA, redundantly) ----
        {
            // zero the buffer consumed at E(t-1); next written at C(t+2) —
            // ordered by barrier(t+1) on both sides (see triple-buffer proof)
            if (tid < 16) {
                float4 z4 = make_float4(0.f, 0.f, 0.f, 0.f);
                *(float4*)&g_zin[(t + 2) % 3][cta * 64 + tid * 4] = z4;
            }
            const float* zr = &g_zin[t % 3][eb * NOUT + ec4 * 32];
            float ze[32];
#pragma unroll
            for (int q = 0; q < 8; q++) {
                float4 v = *(const float4*)&zr[q * 4];
                ze[q * 4 + 0] = v.x; ze[q * 4 + 1] = v.y;
                ze[q * 4 + 2] = v.z; ze[q * 4 + 3] = v.w;
            }
            float m = -1e30f;
#pragma unroll
            for (int j = 0; j < 32; j++) {
                u[j] = 0.9f * u[j] + ze[j] + sBias[(j << 2) | ec4];
                m = fmaxf(m, u[j]);
            }
            m = fmaxf(m, __shfl_xor_sync(0xffffffffu, m, 1));
            m = fmaxf(m, __shfl_xor_sync(0xffffffffu, m, 2));
            float s = 0.f;
#pragma unroll
            for (int j = 0; j < 32; j++) { ze[j] = __expf(u[j] - m); s += ze[j]; }
            s += __shfl_xor_sync(0xffffffffu, s, 1);
            s += __shfl_xor_sync(0xffffffffu, s, 2);
            float inv = 1.f / s;
#pragma unroll
            for (int j = 0; j < 32; j++) {
                float z = ze[j] * inv;
                ze[j] = z;
                sZ[eb][(j << 2) | ec4] = z;
            }
            // output: CTAs 0..7 each own 8 batch rows (one warp active per CTA)
            if (cta < 8 && (eb >> 3) == cta) {
                float* dst = out + (size_t)t * (B * NOUT) + eb * NOUT + ec4 * 32;
#pragma unroll
                for (int q = 0; q < 8; q++)
                    *(float4*)&dst[q * 4] = make_float4(ze[q * 4], ze[q * 4 + 1],
                                                        ze[q * 4 + 2], ze[q * 4 + 3]);
                if (t == T_STEPS - 1 && out_size >= (T_STEPS + 1) * B * NOUT) {
                    float* du = out + (size_t)T_STEPS * (B * NOUT) + eb * NOUT + ec4 * 32;
#pragma unroll
                    for (int q = 0; q < 8; q++)
                        *(float4*)&du[q * 4] = make_float4(u[q * 4], u[q * 4 + 1],
                                                           u[q * 4 + 2], u[q * 4 + 3]);
                }
            }
        }
        __syncthreads();
        // post-mean for step t (consumed by stage B of t+1)
        if (tid < NOUT) {
            int iv = ILV(tid);
            float s = 0.f;
#pragma unroll 8
            for (int b = 0; b < B; b++) s += sZ[b][iv];
            sPm[iv] = s * (1.f / B);
        }
        __syncthreads();
    }
}

extern "C" void kernel_launch(void* const* d_in, const int* in_sizes, int n_in,
                              void* d_out, int out_size) {
    const float* spikes = nullptr;
    const float* weight = nullptr;
    const float* bias   = nullptr;
    for (int i = 0; i < n_in; i++) {
        long n = in_sizes[i];
        if      (n == (long)T_STEPS * B * NIN) spikes = (const float*)d_in[i];
        else if (n == (long)NOUT * NIN)        weight = (const float*)d_in[i];
        else if (n == (long)NOUT)              bias   = (const float*)d_in[i];
    }
    init_kernel<<<96, 256>>>();
    psp_kernel<<<64, 512>>>(spikes);
    snn_kernel<<<NCTA, TPB>>>(weight, bias, (float*)d_out, out_size);
}